// round 8
// baseline (speedup 1.0000x reference)
#include <cuda_runtime.h>

// Packed fp32x2 FMA (Blackwell sm_103a): 2x fp32 throughput vs scalar FFMA.
#define FMA2(d, a, b, c) \
    asm("fma.rn.f32x2 %0, %1, %2, %3;" : "=l"(d) : "l"(a), "l"(b), "l"(c))

// Problem constants (shapes fixed by the dataset)
// imgs: (32, 3, 512, 512) f32; weight: (512, 16384) f32; bias: (512) f32
// feats: (32, 16384) f32 ; out: (32, 512) f32
#define BATCH    32
#define KDIM     16384
#define NDIM     512
#define NSPLIT   128      // split-K factor
#define KCHUNK   128      // K per GEMM block  (NSPLIT*KCHUNK == KDIM)
#define KS       32       // K per smem stage
#define NT       128      // N tile per GEMM block

// Scratch (device globals: no allocation allowed in kernel_launch)
__device__ float g_feats[BATCH * KDIM];                 // 2 MB, [b][k]
__device__ float g_part[NSPLIT * BATCH * NDIM];         // 8 MB, [ks][m][n]

// ---------------------------------------------------------------------------
// Kernel 1: per-8x8-block features. Only dct[0, 0:4] survives:
//   s[l] = sum_a X[a][l];  f_m = (1/8) * sum_l s[l] * cos(pi*m*l/4)
// One thread per (batch, block). tid = b*4096 + (i*64 + j) so both the image
// reads and the float4 feats stores are coalesced.
// ---------------------------------------------------------------------------
__global__ __launch_bounds__(256) void feats_kernel(const float* __restrict__ img)
{
    int tid = blockIdx.x * 256 + threadIdx.x;   // 0 .. 131071
    int b  = tid >> 12;                          // batch
    int ij = tid & 4095;                         // block index (i*64 + j)
    int i  = ij >> 6;
    int j  = ij & 63;

    // channel 0 of image b: offset b*3*512*512
    const float* p = img + (size_t)b * 786432 + (size_t)(i * 8) * 512 + j * 8;

    float s0 = 0.f, s1 = 0.f, s2 = 0.f, s3 = 0.f;
    float s4 = 0.f, s5 = 0.f, s6 = 0.f, s7 = 0.f;
#pragma unroll
    for (int r = 0; r < 8; r++) {
        float4 lo = *(const float4*)(p + r * 512);
        float4 hi = *(const float4*)(p + r * 512 + 4);
        s0 += lo.x; s1 += lo.y; s2 += lo.z; s3 += lo.w;
        s4 += hi.x; s5 += hi.y; s6 += hi.z; s7 += hi.w;
    }

    const float R = 0.70710678118654752f;  // cos(pi/4)
    float e = s0 - s4;
    float o = s1 - s3 - s5 + s7;
    float4 f;
    f.x = 0.125f * (((s0 + s1) + (s2 + s3)) + ((s4 + s5) + (s6 + s7)));
    f.y = 0.125f * (e + R * o);
    f.z = 0.125f * ((s0 - s2) + (s4 - s6));
    f.w = 0.125f * (e - R * o);

    *(float4*)&g_feats[(size_t)b * KDIM + ij * 4] = f;
}

// ---------------------------------------------------------------------------
// Kernel 2: split-K GEMM partials.  part[ks][m][n] = sum_{k in chunk} A[m][k]*W[n][k]
// Block tile: M=32 x N=128 over KCHUNK=128.  grid = (NDIM/NT, NSPLIT) = (4,128).
// Per thread: 4m x 4n accumulators, packed f32x2 over k-pairs (even k in lane0,
// odd k in lane1; folded at the end). Inner loop: 8 LDS.64 + 16 FFMA2 per 32 MACs.
// ---------------------------------------------------------------------------
__global__ __launch_bounds__(256) void gemm_kernel(const float* __restrict__ W)
{
    // Strides chosen so every 8B/16B access is aligned and w-loads are at most
    // 2-way bank conflicted; a-loads are warp-uniform (broadcast).
    __shared__ __align__(16) float As[32 * 36];   // [m][k], stride 36
    __shared__ __align__(16) float Ws[NT * 34];   // [n][k], stride 34

    const int t  = threadIdx.x;
    const int n0 = blockIdx.x * NT;
    const int ks = blockIdx.y;
    const int k0 = ks * KCHUNK;
    const int tx = t & 31;         // n lane
    const int ty = t >> 5;         // m group (0..7)
    const int m0 = ty * 4;

    unsigned long long acc[4][4];
#pragma unroll
    for (int mi = 0; mi < 4; mi++)
#pragma unroll
        for (int q = 0; q < 4; q++) acc[mi][q] = 0ULL;  // packed (+0.f, +0.f)

    for (int kk = 0; kk < KCHUNK; kk += KS) {
        const int kb = k0 + kk;

        // stage A: 32m x 32k (coalesced LDG.128, aligned STS.128)
        {
            int m = t >> 3, kq = t & 7;
            float4 v = *(const float4*)&g_feats[(size_t)m * KDIM + kb + kq * 4];
            *(float4*)&As[m * 36 + kq * 4] = v;
        }
        // stage W: 128n x 32k in 4 passes (coalesced LDG.128, STS.64 pairs)
#pragma unroll
        for (int p = 0; p < 4; p++) {
            int n = (t >> 3) + p * 32, kq = t & 7;
            float4 v = *(const float4*)&W[(size_t)(n0 + n) * KDIM + kb + kq * 4];
            float2* dst = (float2*)&Ws[n * 34 + kq * 4];
            dst[0] = make_float2(v.x, v.y);
            dst[1] = make_float2(v.z, v.w);
        }
        __syncthreads();

#pragma unroll
        for (int k = 0; k < KS; k += 2) {
            unsigned long long a2[4], w2[4];
#pragma unroll
            for (int mi = 0; mi < 4; mi++)
                a2[mi] = *(const unsigned long long*)&As[(m0 + mi) * 36 + k];
#pragma unroll
            for (int q = 0; q < 4; q++)
                w2[q] = *(const unsigned long long*)&Ws[(tx + 32 * q) * 34 + k];
#pragma unroll
            for (int mi = 0; mi < 4; mi++)
#pragma unroll
                for (int q = 0; q < 4; q++)
                    FMA2(acc[mi][q], a2[mi], w2[q], acc[mi][q]);
        }
        __syncthreads();
    }

    // fold even/odd-k lanes and write partials (coalesced across tx)
#pragma unroll
    for (int mi = 0; mi < 4; mi++) {
#pragma unroll
        for (int q = 0; q < 4; q++) {
            unsigned long long v = acc[mi][q];
            float lo = __uint_as_float((unsigned int)(v & 0xffffffffULL));
            float hi = __uint_as_float((unsigned int)(v >> 32));
            g_part[(size_t)ks * (BATCH * NDIM) + (m0 + mi) * NDIM + n0 + tx + 32 * q] =
                lo + hi;
        }
    }
}

// ---------------------------------------------------------------------------
// Kernel 3: deterministic split-K reduction + bias.  out[m][n] (16384 values)
// ---------------------------------------------------------------------------
__global__ __launch_bounds__(256) void reduce_kernel(const float* __restrict__ bias,
                                                     float* __restrict__ out)
{
    int i = blockIdx.x * 256 + threadIdx.x;   // 0 .. 16383
    float a0 = 0.f, a1 = 0.f, a2 = 0.f, a3 = 0.f;
#pragma unroll
    for (int ks = 0; ks < NSPLIT; ks += 4) {
        a0 += g_part[(size_t)(ks + 0) * (BATCH * NDIM) + i];
        a1 += g_part[(size_t)(ks + 1) * (BATCH * NDIM) + i];
        a2 += g_part[(size_t)(ks + 2) * (BATCH * NDIM) + i];
        a3 += g_part[(size_t)(ks + 3) * (BATCH * NDIM) + i];
    }
    out[i] = ((a0 + a1) + (a2 + a3)) + bias[i & (NDIM - 1)];
}

// ---------------------------------------------------------------------------
extern "C" void kernel_launch(void* const* d_in, const int* in_sizes, int n_in,
                              void* d_out, int out_size)
{
    const float* img    = (const float*)d_in[0];
    const float* weight = (const float*)d_in[1];
    const float* bias   = (const float*)d_in[2];
    float* out = (float*)d_out;

    feats_kernel<<<512, 256>>>(img);                       // 131072 threads
    gemm_kernel<<<dim3(NDIM / NT, NSPLIT), 256>>>(weight); // (4,128) blocks
    reduce_kernel<<<(BATCH * NDIM) / 256, 256>>>(bias, out);
}

// round 9
// speedup vs baseline: 1.0369x; 1.0369x over previous
#include <cuda_runtime.h>

// Packed fp32x2 FMA (Blackwell sm_103a): 2x fp32 throughput vs scalar FFMA.
#define FMA2(d, a, b, c) \
    asm("fma.rn.f32x2 %0, %1, %2, %3;" : "=l"(d) : "l"(a), "l"(b), "l"(c))

// Problem constants (shapes fixed by the dataset)
// imgs: (32, 3, 512, 512) f32; weight: (512, 16384) f32; bias: (512) f32
// feats: (32, 16384) f32 ; out: (32, 512) f32
#define BATCH    32
#define KDIM     16384
#define NDIM     512
#define NSPLIT   128      // split-K factor
#define KCHUNK   128      // K per GEMM block  (NSPLIT*KCHUNK == KDIM)
#define KS       32       // K per smem stage
#define NT       128      // N tile per GEMM block

// Scratch (device globals: no allocation allowed in kernel_launch)
__device__ float g_feats[BATCH * KDIM];                 // 2 MB, [b][k]
__device__ float g_part[NSPLIT * BATCH * NDIM];         // 8 MB, [ks][m][n]

// ---------------------------------------------------------------------------
// Kernel 1: per-8x8-block features. Only dct[0, 0:4] survives:
//   s[l] = sum_a X[a][l];  f_m = (1/8) * sum_l s[l] * cos(pi*m*l/4)
// One thread per (batch, block). tid = b*4096 + (i*64 + j) so both the image
// reads and the float4 feats stores are coalesced.
// ---------------------------------------------------------------------------
__global__ __launch_bounds__(256) void feats_kernel(const float* __restrict__ img)
{
    int tid = blockIdx.x * 256 + threadIdx.x;   // 0 .. 131071
    int b  = tid >> 12;                          // batch
    int ij = tid & 4095;                         // block index (i*64 + j)
    int i  = ij >> 6;
    int j  = ij & 63;

    // channel 0 of image b: offset b*3*512*512
    const float* p = img + (size_t)b * 786432 + (size_t)(i * 8) * 512 + j * 8;

    float s0 = 0.f, s1 = 0.f, s2 = 0.f, s3 = 0.f;
    float s4 = 0.f, s5 = 0.f, s6 = 0.f, s7 = 0.f;
#pragma unroll
    for (int r = 0; r < 8; r++) {
        float4 lo = *(const float4*)(p + r * 512);
        float4 hi = *(const float4*)(p + r * 512 + 4);
        s0 += lo.x; s1 += lo.y; s2 += lo.z; s3 += lo.w;
        s4 += hi.x; s5 += hi.y; s6 += hi.z; s7 += hi.w;
    }

    const float R = 0.70710678118654752f;  // cos(pi/4)
    float e = s0 - s4;
    float o = s1 - s3 - s5 + s7;
    float4 f;
    f.x = 0.125f * (((s0 + s1) + (s2 + s3)) + ((s4 + s5) + (s6 + s7)));
    f.y = 0.125f * (e + R * o);
    f.z = 0.125f * ((s0 - s2) + (s4 - s6));
    f.w = 0.125f * (e - R * o);

    *(float4*)&g_feats[(size_t)b * KDIM + ij * 4] = f;
}

// ---------------------------------------------------------------------------
// Kernel 2: split-K GEMM partials.  part[ks][m][n] = sum_{k in chunk} A[m][k]*W[n][k]
// Block tile: M=32 x N=128 over KCHUNK=128.  grid = (NDIM/NT, NSPLIT) = (4,128).
// Per thread: 4m x 4n accumulators, packed f32x2 over k-pairs (even k in lane0,
// odd k in lane1; folded at the end). Inner loop: 8 LDS.64 + 16 FFMA2 per 32 MACs.
// ---------------------------------------------------------------------------
__global__ __launch_bounds__(256) void gemm_kernel(const float* __restrict__ W)
{
    // Strides chosen so every 8B/16B access is aligned and w-loads are at most
    // 2-way bank conflicted; a-loads are warp-uniform (broadcast).
    __shared__ __align__(16) float As[32 * 36];   // [m][k], stride 36
    __shared__ __align__(16) float Ws[NT * 34];   // [n][k], stride 34

    const int t  = threadIdx.x;
    const int n0 = blockIdx.x * NT;
    const int ks = blockIdx.y;
    const int k0 = ks * KCHUNK;
    const int tx = t & 31;         // n lane
    const int ty = t >> 5;         // m group (0..7)
    const int m0 = ty * 4;

    unsigned long long acc[4][4];
#pragma unroll
    for (int mi = 0; mi < 4; mi++)
#pragma unroll
        for (int q = 0; q < 4; q++) acc[mi][q] = 0ULL;  // packed (+0.f, +0.f)

    for (int kk = 0; kk < KCHUNK; kk += KS) {
        const int kb = k0 + kk;

        // stage A: 32m x 32k (coalesced LDG.128, aligned STS.128)
        {
            int m = t >> 3, kq = t & 7;
            float4 v = *(const float4*)&g_feats[(size_t)m * KDIM + kb + kq * 4];
            *(float4*)&As[m * 36 + kq * 4] = v;
        }
        // stage W: 128n x 32k in 4 passes (coalesced LDG.128, STS.64 pairs)
#pragma unroll
        for (int p = 0; p < 4; p++) {
            int n = (t >> 3) + p * 32, kq = t & 7;
            float4 v = *(const float4*)&W[(size_t)(n0 + n) * KDIM + kb + kq * 4];
            float2* dst = (float2*)&Ws[n * 34 + kq * 4];
            dst[0] = make_float2(v.x, v.y);
            dst[1] = make_float2(v.z, v.w);
        }
        __syncthreads();

#pragma unroll
        for (int k = 0; k < KS; k += 2) {
            unsigned long long a2[4], w2[4];
#pragma unroll
            for (int mi = 0; mi < 4; mi++)
                a2[mi] = *(const unsigned long long*)&As[(m0 + mi) * 36 + k];
#pragma unroll
            for (int q = 0; q < 4; q++)
                w2[q] = *(const unsigned long long*)&Ws[(tx + 32 * q) * 34 + k];
#pragma unroll
            for (int mi = 0; mi < 4; mi++)
#pragma unroll
                for (int q = 0; q < 4; q++)
                    FMA2(acc[mi][q], a2[mi], w2[q], acc[mi][q]);
        }
        __syncthreads();
    }

    // fold even/odd-k lanes and write partials (coalesced across tx)
#pragma unroll
    for (int mi = 0; mi < 4; mi++) {
#pragma unroll
        for (int q = 0; q < 4; q++) {
            unsigned long long v = acc[mi][q];
            float lo = __uint_as_float((unsigned int)(v & 0xffffffffULL));
            float hi = __uint_as_float((unsigned int)(v >> 32));
            g_part[(size_t)ks * (BATCH * NDIM) + (m0 + mi) * NDIM + n0 + tx + 32 * q] =
                lo + hi;
        }
    }
}

// ---------------------------------------------------------------------------
// Kernel 3: deterministic split-K reduction + bias.  out[m][n] (16384 values)
// ---------------------------------------------------------------------------
__global__ __launch_bounds__(256) void reduce_kernel(const float* __restrict__ bias,
                                                     float* __restrict__ out)
{
    int i = blockIdx.x * 256 + threadIdx.x;   // 0 .. 16383
    float a0 = 0.f, a1 = 0.f, a2 = 0.f, a3 = 0.f;
#pragma unroll
    for (int ks = 0; ks < NSPLIT; ks += 4) {
        a0 += g_part[(size_t)(ks + 0) * (BATCH * NDIM) + i];
        a1 += g_part[(size_t)(ks + 1) * (BATCH * NDIM) + i];
        a2 += g_part[(size_t)(ks + 2) * (BATCH * NDIM) + i];
        a3 += g_part[(size_t)(ks + 3) * (BATCH * NDIM) + i];
    }
    out[i] = ((a0 + a1) + (a2 + a3)) + bias[i & (NDIM - 1)];
}

// ---------------------------------------------------------------------------
extern "C" void kernel_launch(void* const* d_in, const int* in_sizes, int n_in,
                              void* d_out, int out_size)
{
    const float* img    = (const float*)d_in[0];
    const float* weight = (const float*)d_in[1];
    const float* bias   = (const float*)d_in[2];
    float* out = (float*)d_out;

    feats_kernel<<<512, 256>>>(img);                       // 131072 threads
    gemm_kernel<<<dim3(NDIM / NT, NSPLIT), 256>>>(weight); // (4,128) blocks
    reduce_kernel<<<(BATCH * NDIM) / 256, 256>>>(bias, out);
}

// round 10
// speedup vs baseline: 1.1825x; 1.1404x over previous
#include <cuda_runtime.h>

// Packed fp32x2 FMA (Blackwell sm_103a): 2x fp32 throughput vs scalar FFMA.
#define FMA2(d, a, b, c) \
    asm("fma.rn.f32x2 %0, %1, %2, %3;" : "=l"(d) : "l"(a), "l"(b), "l"(c))

// Shapes (fixed): imgs (32,3,512,512) f32; weight (512,16384) f32; bias (512);
// out (32,512) f32.
#define BATCH   32
#define KDIM    16384
#define NDIM    512
#define NSPLIT  128        // K-splits == grid size (single wave on 148 SMs)
#define KPS     16         // k-pairs per W stage (32 k)
#define NSTAGE  4          // stages per block -> KCHUNK = 128 k (64 k-pairs)
#define KP_CHUNK (KPS * NSTAGE)

// smem (u64 units): As2 [64 kp][34] (32 m + 2 pad), Ws 2 x [512 n][17] (16 kp + 1 pad)
#define AS_STRIDE 34
#define WS_STRIDE 17
#define WS_BUF    (NDIM * WS_STRIDE)
#define SMEM_U64  (KP_CHUNK * AS_STRIDE + 2 * WS_BUF)
#define SMEM_BYTES (SMEM_U64 * 8)              // 156,672 B

typedef unsigned long long u64;

__device__ float g_part[NSPLIT * BATCH * NDIM];   // 8 MB split-K partials

__device__ __forceinline__ void cp8(u64* dst, const u64* src) {
    unsigned d = (unsigned)__cvta_generic_to_shared(dst);
    asm volatile("cp.async.ca.shared.global [%0], [%1], 8;\n" :: "r"(d), "l"(src));
}
__device__ __forceinline__ void cp_commit() {
    asm volatile("cp.async.commit_group;\n" ::: "memory");
}
template <int N> __device__ __forceinline__ void cp_wait() {
    asm volatile("cp.async.wait_group %0;\n" :: "n"(N) : "memory");
}
__device__ __forceinline__ u64 packf2(float lo, float hi) {
    u64 v;
    asm("mov.b64 %0, {%1, %2};" : "=l"(v) : "r"(__float_as_uint(lo)), "r"(__float_as_uint(hi)));
    return v;
}

// ---------------------------------------------------------------------------
// Fused feats + split-K GEMM. One block per K-chunk of 128 (= 32 ij-blocks).
// Block tile: M=32 (batch) x N=512 (full) x K=128.  512 threads.
// Thread tile: 8m x 4n over packed k-pairs (even k lane0 / odd k lane1).
//   a-loads: broadcast LDS.128 (warp-uniform), w-loads: LDS.64 stride-17 (2-way max).
// W streamed via cp.async into a 2-stage double buffer.
// ---------------------------------------------------------------------------
__global__ __launch_bounds__(512, 1) void fused_kernel(const float* __restrict__ img,
                                                       const float* __restrict__ Wf)
{
    extern __shared__ u64 sm[];
    u64* As2 = sm;                         // [kp][m] packed A pairs
    u64* Ws  = sm + KP_CHUNK * AS_STRIDE;  // [buf][n][kp]

    const int t  = threadIdx.x;
    const int ks = blockIdx.x;
    const u64* Wu = (const u64*)Wf;             // weight as k-pairs: [n][8192]
    const long kb = (long)ks * KP_CHUNK;        // this chunk's u64 k-offset

    // cp.async mapping: lanes 0-15 cover one n-row's 16 k-pairs (128B line).
    const int cn = t >> 4;     // 0..31 (n offset within r-slab)
    const int ck = t & 15;     // k-pair

    // ---- prefetch W stages 0,1 ----
#pragma unroll
    for (int s = 0; s < 2; s++) {
        u64* buf = Ws + (s & 1) * WS_BUF;
#pragma unroll
        for (int r = 0; r < 16; r++) {
            int n = r * 32 + cn;
            cp8(&buf[n * WS_STRIDE + ck], &Wu[(long)n * (KDIM / 2) + kb + s * KPS + ck]);
        }
        cp_commit();
    }

    // ---- feats phase: 1024 units (b, ijl), 2 per thread; overlaps cp.async ----
    // Only dct[0,0:4] of each 8x8 block survives:
    //   s[l] = sum_rows X[r][l];  f_m = (1/8) * sum_l s[l]*cos(pi*m*l/4)
#pragma unroll
    for (int u0 = 0; u0 < 2; u0++) {
        int u   = t + u0 * 512;
        int b   = u >> 5;
        int ijl = u & 31;
        int ij  = ks * 32 + ijl;            // global 8x8-block index (one i per block)
        int i   = ij >> 6, j = ij & 63;
        const float* p = img + (long)b * 786432 + (long)(i * 8) * 512 + j * 8;

        float s0 = 0.f, s1 = 0.f, s2 = 0.f, s3 = 0.f;
        float s4 = 0.f, s5 = 0.f, s6 = 0.f, s7 = 0.f;
#pragma unroll
        for (int r = 0; r < 8; r++) {
            float4 lo = *(const float4*)(p + r * 512);
            float4 hi = *(const float4*)(p + r * 512 + 4);
            s0 += lo.x; s1 += lo.y; s2 += lo.z; s3 += lo.w;
            s4 += hi.x; s5 += hi.y; s6 += hi.z; s7 += hi.w;
        }
        const float R = 0.70710678118654752f;
        float e = s0 - s4;
        float o = s1 - s3 - s5 + s7;
        float f0 = 0.125f * (((s0 + s1) + (s2 + s3)) + ((s4 + s5) + (s6 + s7)));
        float f1 = 0.125f * (e + R * o);
        float f2 = 0.125f * ((s0 - s2) + (s4 - s6));
        float f3 = 0.125f * (e - R * o);

        As2[(2 * ijl    ) * AS_STRIDE + b] = packf2(f0, f1);   // k-pair (4ijl, 4ijl+1)
        As2[(2 * ijl + 1) * AS_STRIDE + b] = packf2(f2, f3);   // k-pair (4ijl+2, 4ijl+3)
    }
    __syncthreads();   // A ready for all stages

    // ---- output mapping: 8m x 4n per thread ----
    const int tx = t & 31;
    const int ty = t >> 5;
    const int m0 = (ty & 3) * 8;                 // 8 m rows
    const int nb = (ty >> 2) * 128 + tx;         // 4 n: nb + 32*q

    u64 acc[8][4];
#pragma unroll
    for (int mi = 0; mi < 8; mi++)
#pragma unroll
        for (int q = 0; q < 4; q++) acc[mi][q] = 0ULL;

    // ---- mainloop over 4 W stages ----
    for (int s = 0; s < NSTAGE; s++) {
        cp_wait<1>();          // stage s complete (groups retire in order)
        __syncthreads();
        const u64* buf = Ws + (s & 1) * WS_BUF;

#pragma unroll
        for (int kpl = 0; kpl < KPS; kpl++) {
            const u64* arow = &As2[(s * KPS + kpl) * AS_STRIDE + m0];
            ulonglong2 A01 = *(const ulonglong2*)(arow);       // m0, m0+1 (broadcast)
            ulonglong2 A23 = *(const ulonglong2*)(arow + 2);
            ulonglong2 A45 = *(const ulonglong2*)(arow + 4);
            ulonglong2 A67 = *(const ulonglong2*)(arow + 6);
            u64 a[8] = {A01.x, A01.y, A23.x, A23.y, A45.x, A45.y, A67.x, A67.y};

            u64 w2[4];
#pragma unroll
            for (int q = 0; q < 4; q++)
                w2[q] = buf[(nb + 32 * q) * WS_STRIDE + kpl];

#pragma unroll
            for (int mi = 0; mi < 8; mi++)
#pragma unroll
                for (int q = 0; q < 4; q++)
                    FMA2(acc[mi][q], a[mi], w2[q], acc[mi][q]);
        }
        __syncthreads();       // everyone done reading buf before overwrite

        if (s + 2 < NSTAGE) {  // refill this buffer with stage s+2
            u64* nbuf = Ws + (s & 1) * WS_BUF;
#pragma unroll
            for (int r = 0; r < 16; r++) {
                int n = r * 32 + cn;
                cp8(&nbuf[n * WS_STRIDE + ck],
                    &Wu[(long)n * (KDIM / 2) + kb + (s + 2) * KPS + ck]);
            }
        }
        cp_commit();           // empty groups on last iters keep wait<1> aligned
    }

    // ---- fold k-pair lanes, write partials (coalesced over tx) ----
    float* outp = g_part + (long)ks * (BATCH * NDIM);
#pragma unroll
    for (int mi = 0; mi < 8; mi++) {
#pragma unroll
        for (int q = 0; q < 4; q++) {
            u64 v = acc[mi][q];
            float lo = __uint_as_float((unsigned)(v & 0xffffffffULL));
            float hi = __uint_as_float((unsigned)(v >> 32));
            outp[(m0 + mi) * NDIM + nb + 32 * q] = lo + hi;
        }
    }
}

// ---------------------------------------------------------------------------
// Deterministic split-K reduction + bias (partials are L2-resident).
// ---------------------------------------------------------------------------
__global__ __launch_bounds__(256) void reduce_kernel(const float* __restrict__ bias,
                                                     float* __restrict__ out)
{
    int i = blockIdx.x * 256 + threadIdx.x;   // 0 .. 16383
    float a0 = 0.f, a1 = 0.f, a2 = 0.f, a3 = 0.f;
#pragma unroll
    for (int ks = 0; ks < NSPLIT; ks += 4) {
        a0 += g_part[(long)(ks + 0) * (BATCH * NDIM) + i];
        a1 += g_part[(long)(ks + 1) * (BATCH * NDIM) + i];
        a2 += g_part[(long)(ks + 2) * (BATCH * NDIM) + i];
        a3 += g_part[(long)(ks + 3) * (BATCH * NDIM) + i];
    }
    out[i] = ((a0 + a1) + (a2 + a3)) + bias[i & (NDIM - 1)];
}

// ---------------------------------------------------------------------------
extern "C" void kernel_launch(void* const* d_in, const int* in_sizes, int n_in,
                              void* d_out, int out_size)
{
    const float* img    = (const float*)d_in[0];
    const float* weight = (const float*)d_in[1];
    const float* bias   = (const float*)d_in[2];
    float* out = (float*)d_out;

    // 157 KB dynamic smem (> 48 KB default) — opt in every call (idempotent,
    // not a stream op, so safe under graph capture).
    cudaFuncSetAttribute(fused_kernel,
                         cudaFuncAttributeMaxDynamicSharedMemorySize, SMEM_BYTES);

    fused_kernel<<<NSPLIT, 512, SMEM_BYTES>>>(img, weight);
    reduce_kernel<<<(BATCH * NDIM) / 256, 256>>>(bias, out);
}